// round 4
// baseline (speedup 1.0000x reference)
#include <cuda_runtime.h>
#include <cuda_bf16.h>
#include <math.h>
#include <stdint.h>

// ---------------- problem constants ----------------
#define NT      32768
#define NPER    2048
#define IN_C    256
#define DIM     128
#define H1DIM   256
#define NATOMS  20
#define ENC_H   100
#define OUTC    6
#define MASK_WORDS (NT * 64)
#define TAU     1.5e-3f

// ---------------- scratch ----------------
__device__ unsigned g_mask[MASK_WORDS];
__device__ float    g_stats[2 * IN_C];
__device__ int      g_ids[NT];
__device__ int      g_flag[NT];
__device__ int      g_nflag;
__device__ float    g_b1f[H1DIM];
__device__ float    g_a1p[128];
__device__ float    g_TW[NATOMS * DIM];
__device__ float    g_W1f[IN_C * H1DIM];            // fp32 folded W1 (fallback)
__device__ float    g_h2[(size_t)NT * DIM];
__device__ float    g_t1[(size_t)NT * 128];
// pre-split bf16 operands, [N][K] (k-contiguous) layout
__device__ __align__(16) __nv_bfloat16 g_W1thi[H1DIM * IN_C];
__device__ __align__(16) __nv_bfloat16 g_W1tlo[H1DIM * IN_C];
__device__ __align__(16) __nv_bfloat16 g_W2thi[DIM * H1DIM];
__device__ __align__(16) __nv_bfloat16 g_W2tlo[DIM * H1DIM];
__device__ __align__(16) __nv_bfloat16 g_A1thi[128 * 128];
__device__ __align__(16) __nv_bfloat16 g_A1tlo[128 * 128];
// h1 stored pre-split
__device__ __align__(16) __nv_bfloat16 g_h1hi[(size_t)NT * H1DIM];
__device__ __align__(16) __nv_bfloat16 g_h1lo[(size_t)NT * H1DIM];

// ---------------- helpers ----------------
__device__ __forceinline__ float gelu(float x) {
    return 0.5f * x * (1.0f + erff(x * 0.70710678118654752f));
}
__device__ __forceinline__ uint32_t smem_u32(const void* p) {
    uint32_t a;
    asm("{ .reg .u64 t; cvta.to.shared.u64 t, %1; cvt.u32.u64 %0, t; }" : "=r"(a) : "l"(p));
    return a;
}
__device__ __forceinline__ void split2(float v, __nv_bfloat16& h, __nv_bfloat16& l) {
    h = __float2bfloat16_rn(v);
    l = __float2bfloat16_rn(v - __bfloat162float(h));
}
__device__ __forceinline__ unsigned pkb(__nv_bfloat16 a, __nv_bfloat16 b) {
    __nv_bfloat162 t = __halves2bfloat162(a, b);
    return *reinterpret_cast<unsigned*>(&t);
}
// swizzled byte offset inside a 128-row x 64-bf16 (128B/row) smem tile
__device__ __forceinline__ uint32_t sw(int r, int kb) {
    return (uint32_t)(r * 128) + (uint32_t)(kb ^ ((r & 7) << 4));
}
__device__ __forceinline__ void ldsm4(uint32_t* r, uint32_t addr) {
    asm volatile("ldmatrix.sync.aligned.m8n8.x4.shared.b16 {%0,%1,%2,%3}, [%4];"
        : "=r"(r[0]), "=r"(r[1]), "=r"(r[2]), "=r"(r[3]) : "r"(addr));
}
#define MMA(c, A, b0, b1) asm volatile( \
    "mma.sync.aligned.m16n8k16.row.col.f32.bf16.bf16.f32 " \
    "{%0,%1,%2,%3},{%4,%5,%6,%7},{%8,%9},{%0,%1,%2,%3};" \
    : "+f"((c)[0]), "+f"((c)[1]), "+f"((c)[2]), "+f"((c)[3]) \
    : "r"((A)[0]), "r"((A)[1]), "r"((A)[2]), "r"((A)[3]), "r"(b0), "r"(b1))

// ---------------- K0: zero mask + stats + flag count ----------------
__global__ void k_zero() {
    int i = blockIdx.x * blockDim.x + threadIdx.x;
    if (i < MASK_WORDS) g_mask[i] = 0u;
    if (i < 2 * IN_C)   g_stats[i] = 0.0f;
    if (i == 0)         g_nflag = 0;
}

// ---------------- K1: BN stats ----------------
__global__ void k_bn_stats(const float* __restrict__ x) {
    int c  = threadIdx.x;
    int r0 = blockIdx.x * 128;
    float s = 0.f, q = 0.f;
    #pragma unroll 4
    for (int r = 0; r < 128; r++) {
        float v = x[(size_t)(r0 + r) * IN_C + c];
        s += v; q += v * v;
    }
    atomicAdd(&g_stats[c], s);
    atomicAdd(&g_stats[IN_C + c], q);
}

// ---------------- K2: fold BN into W1 -> fp32 + split [N][K] tiles + b1f ----------------
__global__ void k_fold(const float* __restrict__ W1, const float* __restrict__ b1,
                       const float* __restrict__ gamma, const float* __restrict__ beta) {
    int j = blockIdx.x;      // output col n (0..255)
    int c = threadIdx.x;     // input channel k (0..255)
    float mean = g_stats[c] * (1.0f / NT);
    float var  = g_stats[IN_C + c] * (1.0f / NT) - mean * mean;
    float inv  = rsqrtf(var + 1e-5f);
    float sc   = gamma[c] * inv;
    float sh   = beta[c] - mean * sc;
    float w    = W1[c * H1DIM + j];
    float wv   = sc * w;
    g_W1f[c * H1DIM + j] = wv;
    __nv_bfloat16 h, l;
    split2(wv, h, l);
    g_W1thi[j * IN_C + c] = h;
    g_W1tlo[j * IN_C + c] = l;

    __shared__ float red[256];
    red[c] = sh * w;
    __syncthreads();
    for (int o = 128; o > 0; o >>= 1) {
        if (c < o) red[c] += red[c + o];
        __syncthreads();
    }
    if (c == 0) g_b1f[j] = b1[j] + red[0];
}

// ---------------- K3: TW = embed[0:20] @ W_msg (warp per output) ----------------
__global__ void k_tw2(const float* __restrict__ embed, const float* __restrict__ Wm) {
    int w = (blockIdx.x * blockDim.x + threadIdx.x) >> 5;
    int lane = threadIdx.x & 31;
    if (w < NATOMS * DIM) {
        int a = w >> 7, j = w & 127;
        float s = 0.f;
        #pragma unroll
        for (int i = 0; i < 4; i++) {
            int k = lane * 4 + i;
            s += embed[a * DIM + k] * Wm[k * DIM + j];
        }
        #pragma unroll
        for (int o = 16; o > 0; o >>= 1) s += __shfl_xor_sync(0xffffffffu, s, o);
        if (lane == 0) g_TW[w] = s;
    }
}

// ---------------- K3b: split W2 + padded A1 to [N][K]; a1p ----------------
__global__ void k_prep(const float* __restrict__ W2, const float* __restrict__ A1,
                       const float* __restrict__ a1) {
    int idx = blockIdx.x * blockDim.x + threadIdx.x;   // 192*256 = 49152
    if (idx < DIM * H1DIM) {                           // 32768: W2t
        int n = idx >> 8, k = idx & 255;
        __nv_bfloat16 h, l;
        split2(W2[k * DIM + n], h, l);
        g_W2thi[n * H1DIM + k] = h;
        g_W2tlo[n * H1DIM + k] = l;
    } else if (idx < DIM * H1DIM + 128 * 128) {        // 16384: A1t
        int t = idx - DIM * H1DIM;
        int n = t >> 7, k = t & 127;
        float v = (n < ENC_H) ? A1[k * ENC_H + n] : 0.0f;
        __nv_bfloat16 h, l;
        split2(v, h, l);
        g_A1thi[n * 128 + k] = h;
        g_A1tlo[n * 128 + k] = l;
        if (k == 0) g_a1p[n] = (n < ENC_H) ? a1[n] : 0.0f;
    }
}

// ---------------- K4: edge scatter ----------------
__global__ void k_edges(const int* __restrict__ ei, int E) {
    int e = blockIdx.x * blockDim.x + threadIdx.x;
    if (e < E) {
        int s = ei[e];
        int d = ei[E + e];
        if ((s >> 11) == (d >> 11)) {
            unsigned bit = ((unsigned)s << 11) + (unsigned)(d & (NPER - 1));
            atomicOr(&g_mask[bit >> 5], 1u << (bit & 31));
        }
    }
}

// ---------------- HMMA bf16x2 GEMM: C[128x128 tile] = gelu(A@B^T + bias) ----------------
// 3 error terms: A0B0 + A0B1 + A1B0.  A fp32 (ASRC=0) or pre-split bf16 (ASRC=1).
// B pre-split bf16 [N][K].  EPI=0: write split bf16 (h1).  EPI=1: write fp32.
template<int KDIM, int ASRC, int EPI>
__global__ void __launch_bounds__(256, 1) k_mma(
    const float* __restrict__ Af,
    const __nv_bfloat16* __restrict__ Ahi, const __nv_bfloat16* __restrict__ Alo,
    const __nv_bfloat16* __restrict__ Bhi, const __nv_bfloat16* __restrict__ Blo,
    const float* __restrict__ bias,
    float* __restrict__ Cf, __nv_bfloat16* __restrict__ Chi,
    __nv_bfloat16* __restrict__ Clo, int Nfull)
{
    extern __shared__ char smraw[];
    char* sA0 = smraw;
    char* sA1 = smraw + 16384;
    char* sB0 = smraw + 32768;
    char* sB1 = smraw + 49152;
    uint32_t sbase = smem_u32(smraw);

    int tid = threadIdx.x;
    int nt = blockIdx.x, mt = blockIdx.y;
    int w = tid >> 5, l = tid & 31;
    int mw = w >> 1, nw = w & 1;          // warp grid 4(m) x 2(n); warp tile 32x64

    float acc[2][8][4] = {};

    for (int kc = 0; kc < KDIM / 64; kc++) {
        // ---- A tiles ----
        if (ASRC == 0) {
            #pragma unroll
            for (int i = 0; i < 8; i++) {
                int idx = tid + i * 256;
                int r = idx >> 4, k4 = idx & 15;
                float4 v = *(const float4*)(Af + (size_t)(mt * 128 + r) * KDIM + kc * 64 + k4 * 4);
                __nv_bfloat16 h0, l0, h1, l1, h2, l2, h3, l3;
                split2(v.x, h0, l0); split2(v.y, h1, l1);
                split2(v.z, h2, l2); split2(v.w, h3, l3);
                uint32_t o = sw(r, k4 * 8);
                *(uint2*)(sA0 + o) = make_uint2(pkb(h0, h1), pkb(h2, h3));
                *(uint2*)(sA1 + o) = make_uint2(pkb(l0, l1), pkb(l2, l3));
            }
        } else {
            #pragma unroll
            for (int i = 0; i < 4; i++) {
                int idx = tid + i * 256;
                int r = idx >> 3, k8 = idx & 7;
                size_t so = (size_t)(mt * 128 + r) * KDIM + kc * 64 + k8 * 8;
                uint32_t o = sw(r, k8 * 16);
                *(uint4*)(sA0 + o) = *(const uint4*)(Ahi + so);
                *(uint4*)(sA1 + o) = *(const uint4*)(Alo + so);
            }
        }
        // ---- B tiles ----
        #pragma unroll
        for (int i = 0; i < 4; i++) {
            int idx = tid + i * 256;
            int n = idx >> 3, k8 = idx & 7;
            size_t so = (size_t)(nt * 128 + n) * KDIM + kc * 64 + k8 * 8;
            uint32_t o = sw(n, k8 * 16);
            *(uint4*)(sB0 + o) = *(const uint4*)(Bhi + so);
            *(uint4*)(sB1 + o) = *(const uint4*)(Blo + so);
        }
        __syncthreads();

        #pragma unroll
        for (int kk = 0; kk < 4; kk++) {
            int kbyte = kk * 32;
            uint32_t a0[2][4], a1[2][4];
            #pragma unroll
            for (int mi = 0; mi < 2; mi++) {
                int row = mw * 32 + mi * 16 + ((l >> 3) & 1) * 8 + (l & 7);
                int kb2 = kbyte + (l >> 4) * 16;
                uint32_t o = sw(row, kb2);
                ldsm4(a0[mi], sbase + o);
                ldsm4(a1[mi], sbase + 16384 + o);
            }
            uint32_t b0[4][4], b1[4][4];
            #pragma unroll
            for (int nb = 0; nb < 4; nb++) {
                int n = nw * 64 + nb * 16 + ((l >> 4) & 1) * 8 + (l & 7);
                int kb2 = kbyte + ((l >> 3) & 1) * 16;
                uint32_t o = sw(n, kb2);
                ldsm4(b0[nb], sbase + 32768 + o);
                ldsm4(b1[nb], sbase + 49152 + o);
            }
            #pragma unroll
            for (int mi = 0; mi < 2; mi++)
                #pragma unroll
                for (int nb = 0; nb < 4; nb++)
                    #pragma unroll
                    for (int h = 0; h < 2; h++) {
                        int n8 = nb * 2 + h;
                        MMA(acc[mi][n8], a0[mi], b0[nb][h * 2], b0[nb][h * 2 + 1]);
                        MMA(acc[mi][n8], a0[mi], b1[nb][h * 2], b1[nb][h * 2 + 1]);
                        MMA(acc[mi][n8], a1[mi], b0[nb][h * 2], b0[nb][h * 2 + 1]);
                    }
        }
        __syncthreads();
    }

    // ---- epilogue ----
    #pragma unroll
    for (int mi = 0; mi < 2; mi++) {
        #pragma unroll
        for (int n8 = 0; n8 < 8; n8++) {
            int gcol = nt * 128 + nw * 64 + n8 * 8 + (l & 3) * 2;
            int row0 = mt * 128 + mw * 32 + mi * 16 + (l >> 2);
            float b0v = bias[gcol], b1v = bias[gcol + 1];
            #pragma unroll
            for (int hh = 0; hh < 2; hh++) {
                int node = row0 + hh * 8;
                float v0 = gelu(acc[mi][n8][hh * 2 + 0] + b0v);
                float v1 = gelu(acc[mi][n8][hh * 2 + 1] + b1v);
                if (EPI == 0) {
                    __nv_bfloat16 h0, l0, h1, l1;
                    split2(v0, h0, l0); split2(v1, h1, l1);
                    size_t o = (size_t)node * Nfull + gcol;
                    *(__nv_bfloat162*)(Chi + o) = __halves2bfloat162(h0, h1);
                    *(__nv_bfloat162*)(Clo + o) = __halves2bfloat162(l0, l1);
                } else {
                    *(float2*)(Cf + (size_t)node * Nfull + gcol) = make_float2(v0, v1);
                }
            }
        }
    }
}

// ---------------- K7: logits + argmax + ambiguity flag ----------------
__global__ void __launch_bounds__(256)
k_logits_argmax(const float* __restrict__ W3, const float* __restrict__ b3) {
    __shared__ float rows[64][129];
    __shared__ float W3s[128 * NATOMS];
    __shared__ float b3s[NATOMS];
    int tid = threadIdx.x;
    int rbase = blockIdx.x * 64;
    const float* src = g_h2 + (size_t)rbase * DIM;
    for (int i = tid; i < 64 * 128; i += 256) rows[i >> 7][i & 127] = src[i];
    for (int i = tid; i < 128 * NATOMS; i += 256) W3s[i] = W3[i];
    if (tid < NATOMS) b3s[tid] = b3[tid];
    __syncthreads();

    int r = tid >> 2, part = tid & 3;
    float acc[5] = {0, 0, 0, 0, 0};
    for (int k = 0; k < 128; k++) {
        float v = rows[r][k];
        #pragma unroll
        for (int j = 0; j < 5; j++) acc[j] += v * W3s[k * NATOMS + part * 5 + j];
    }
    float b1 = -1e30f, b2 = -1e30f; int i1 = 0;
    #pragma unroll
    for (int j = 0; j < 5; j++) {
        int col = part * 5 + j;
        float lg = acc[j] + b3s[col];
        if (lg > b1) { b2 = b1; b1 = lg; i1 = col; }
        else if (lg > b2) b2 = lg;
    }
    #pragma unroll
    for (int o = 1; o <= 2; o <<= 1) {
        float ob1 = __shfl_xor_sync(0xffffffffu, b1, o);
        int   oi1 = __shfl_xor_sync(0xffffffffu, i1, o);
        float ob2 = __shfl_xor_sync(0xffffffffu, b2, o);
        if (ob1 > b1 || (ob1 == b1 && oi1 < i1)) {
            b2 = fmaxf(b1, ob2); b1 = ob1; i1 = oi1;
        } else {
            b2 = fmaxf(b2, ob1);
        }
    }
    if (part == 0) {
        int node = rbase + r;
        g_ids[node] = i1;
        if (b1 - b2 < TAU) {
            int p = atomicAdd(&g_nflag, 1);
            g_flag[p] = node;
        }
    }
}

// ---------------- K7b: fp32 recompute of flagged (ambiguous) nodes ----------------
__global__ void __launch_bounds__(256)
k_fix(const float* __restrict__ x, const float* __restrict__ W2,
      const float* __restrict__ b2, const float* __restrict__ W3,
      const float* __restrict__ b3) {
    __shared__ float xs[256], h1s[256], part[256], h2s[128], lg[NATOMS];
    int tid = threadIdx.x;
    int nf = g_nflag;
    for (int fi = blockIdx.x; fi < nf; fi += gridDim.x) {
        int node = g_flag[fi];
        xs[tid] = x[(size_t)node * IN_C + tid];
        __syncthreads();
        float s = 0.f;
        #pragma unroll 8
        for (int c = 0; c < 256; c++) s += xs[c] * g_W1f[c * H1DIM + tid];
        h1s[tid] = gelu(s + g_b1f[tid]);
        __syncthreads();
        {
            int j = tid & 127, p = tid >> 7;
            float s2 = 0.f;
            #pragma unroll 8
            for (int c = p * 128; c < p * 128 + 128; c++) s2 += h1s[c] * W2[c * DIM + j];
            part[tid] = s2;
        }
        __syncthreads();
        if (tid < 128) h2s[tid] = gelu(part[tid] + part[128 + tid] + b2[tid]);
        __syncthreads();
        if (tid < NATOMS) {
            float s3 = b3[tid];
            #pragma unroll 8
            for (int k = 0; k < 128; k++) s3 += h2s[k] * W3[k * NATOMS + tid];
            lg[tid] = s3;
        }
        __syncthreads();
        if (tid == 0) {
            float best = lg[0]; int bi = 0;
            for (int a = 1; a < NATOMS; a++) if (lg[a] > best) { best = lg[a]; bi = a; }
            g_ids[node] = bi;
        }
        __syncthreads();
    }
}

// ---------------- K8: aggregation -> z, coords ----------------
__global__ void __launch_bounds__(256)
k_agg(const float* __restrict__ b_msg, const float* __restrict__ w_coor,
      const float* __restrict__ coords, float* __restrict__ out_z,
      float* __restrict__ out_coors) {
    __shared__ float TWs[NATOMS * DIM];
    __shared__ float wcs[DIM * 3];
    __shared__ float bms[DIM];
    __shared__ int   hist[8][NATOMS];
    int tid = threadIdx.x;
    for (int i = tid; i < NATOMS * DIM; i += 256) TWs[i] = g_TW[i];
    for (int i = tid; i < DIM * 3; i += 256)      wcs[i] = w_coor[i];
    for (int i = tid; i < DIM; i += 256)          bms[i] = b_msg[i];
    __syncthreads();

    int warp = tid >> 5, lane = tid & 31;
    int* myhist = hist[warp];
    int wglobal = blockIdx.x * 8 + warp;
    int wstride = gridDim.x * 8;
    int d0 = lane * 4;

    for (int node = wglobal; node < NT; node += wstride) {
        if (lane < NATOMS) myhist[lane] = 0;
        __syncwarp();
        int base = node & ~(NPER - 1);
        int deg = 0;
        #pragma unroll
        for (int half = 0; half < 2; half++) {
            int w = lane + half * 32;
            unsigned m = g_mask[(size_t)node * 64 + w];
            deg += __popc(m);
            while (m) {
                int b = __ffs(m) - 1;
                m &= m - 1;
                int id = g_ids[base + w * 32 + b];
                atomicAdd(&myhist[id], 1);
            }
        }
        deg = __reduce_add_sync(0xffffffffu, deg);
        __syncwarp();
        float invdeg = 1.0f / (float)(deg > 0 ? deg : 1);
        int myid = g_ids[node];

        float4 s = make_float4(0.f, 0.f, 0.f, 0.f);
        #pragma unroll
        for (int a = 0; a < NATOMS; a++) {
            float cf = (float)myhist[a];
            float4 t = *(const float4*)&TWs[a * DIM + d0];
            s.x += cf * t.x; s.y += cf * t.y; s.z += cf * t.z; s.w += cf * t.w;
        }
        float4 own = *(const float4*)&TWs[myid * DIM + d0];
        float h0 = gelu(bms[d0 + 0] + own.x + invdeg * s.x);
        float h1 = gelu(bms[d0 + 1] + own.y + invdeg * s.y);
        float h2 = gelu(bms[d0 + 2] + own.z + invdeg * s.z);
        float h3 = gelu(bms[d0 + 3] + own.w + invdeg * s.w);
        *(float4*)&out_z[(size_t)node * DIM + d0] = make_float4(h0, h1, h2, h3);

        float p0 = h0 * wcs[(d0 + 0) * 3 + 0] + h1 * wcs[(d0 + 1) * 3 + 0]
                 + h2 * wcs[(d0 + 2) * 3 + 0] + h3 * wcs[(d0 + 3) * 3 + 0];
        float p1 = h0 * wcs[(d0 + 0) * 3 + 1] + h1 * wcs[(d0 + 1) * 3 + 1]
                 + h2 * wcs[(d0 + 2) * 3 + 1] + h3 * wcs[(d0 + 3) * 3 + 1];
        float p2 = h0 * wcs[(d0 + 0) * 3 + 2] + h1 * wcs[(d0 + 1) * 3 + 2]
                 + h2 * wcs[(d0 + 2) * 3 + 2] + h3 * wcs[(d0 + 3) * 3 + 2];
        #pragma unroll
        for (int o = 16; o > 0; o >>= 1) {
            p0 += __shfl_xor_sync(0xffffffffu, p0, o);
            p1 += __shfl_xor_sync(0xffffffffu, p1, o);
            p2 += __shfl_xor_sync(0xffffffffu, p2, o);
        }
        if (lane == 0) {
            out_coors[(size_t)node * 3 + 0] = coords[(size_t)node * 3 + 0] + tanhf(p0);
            out_coors[(size_t)node * 3 + 1] = coords[(size_t)node * 3 + 1] + tanhf(p1);
            out_coors[(size_t)node * 3 + 2] = coords[(size_t)node * 3 + 2] + tanhf(p2);
        }
    }
}

// ---------------- K10: angles head ----------------
__global__ void __launch_bounds__(256)
k_angles(const float* __restrict__ A2, const float* __restrict__ a2,
         const float* __restrict__ dyt_alpha, const float* __restrict__ dyt_w,
         const float* __restrict__ dyt_b, float* __restrict__ out_angles) {
    __shared__ float rows[64][129];
    __shared__ float A2s[ENC_H * OUTC];
    __shared__ float a2s[OUTC];
    int tid = threadIdx.x;
    int rbase = blockIdx.x * 64;
    const float* src = g_t1 + (size_t)rbase * 128;
    for (int i = tid; i < 64 * 128; i += 256) rows[i >> 7][i & 127] = src[i];
    for (int i = tid; i < ENC_H * OUTC; i += 256) A2s[i] = A2[i];
    if (tid < OUTC) a2s[tid] = a2[tid];
    __syncthreads();

    if (tid < 64) {
        float alpha = dyt_alpha[0];
        float acc[OUTC] = {0, 0, 0, 0, 0, 0};
        for (int k = 0; k < ENC_H; k++) {
            float v = rows[tid][k];
            #pragma unroll
            for (int c = 0; c < OUTC; c++) acc[c] += v * A2s[k * OUTC + c];
        }
        int node = rbase + tid;
        #pragma unroll
        for (int c = 0; c < OUTC; c++) {
            float t = gelu(acc[c] + a2s[c]);
            float u = tanhf(alpha * t) * dyt_w[c] + dyt_b[c];
            out_angles[(size_t)node * OUTC + c] = tanhf(u);
        }
    }
}

// ---------------- launch ----------------
#define GSMEM 65536
extern "C" void kernel_launch(void* const* d_in, const int* in_sizes, int n_in,
                              void* d_out, int out_size) {
    const float* x_res     = (const float*)d_in[0];
    const float* coords    = (const float*)d_in[1];
    const int*   edge_idx  = (const int*)  d_in[2];
    const float* bn_gamma  = (const float*)d_in[4];
    const float* bn_beta   = (const float*)d_in[5];
    const float* W1        = (const float*)d_in[6];
    const float* b1        = (const float*)d_in[7];
    const float* W2        = (const float*)d_in[8];
    const float* b2        = (const float*)d_in[9];
    const float* W3        = (const float*)d_in[10];
    const float* b3        = (const float*)d_in[11];
    const float* embed     = (const float*)d_in[12];
    const float* W_msg     = (const float*)d_in[13];
    const float* b_msg     = (const float*)d_in[14];
    const float* w_coor    = (const float*)d_in[15];
    const float* A1        = (const float*)d_in[16];
    const float* a1        = (const float*)d_in[17];
    const float* A2        = (const float*)d_in[18];
    const float* a2        = (const float*)d_in[19];
    const float* dyt_alpha = (const float*)d_in[20];
    const float* dyt_w     = (const float*)d_in[21];
    const float* dyt_b     = (const float*)d_in[22];
    int E = in_sizes[2] / 2;

    float* out        = (float*)d_out;
    float* out_angles = out;
    float* out_z      = out + (size_t)NT * OUTC;
    float* out_coors  = out_z + (size_t)NT * DIM;

    float* h2p;  cudaGetSymbolAddress((void**)&h2p,  g_h2);
    float* t1p;  cudaGetSymbolAddress((void**)&t1p,  g_t1);
    float* b1fp; cudaGetSymbolAddress((void**)&b1fp, g_b1f);
    float* a1pp; cudaGetSymbolAddress((void**)&a1pp, g_a1p);
    __nv_bfloat16 *W1h, *W1l, *W2h, *W2l, *A1h, *A1l, *h1h, *h1l;
    cudaGetSymbolAddress((void**)&W1h, g_W1thi);
    cudaGetSymbolAddress((void**)&W1l, g_W1tlo);
    cudaGetSymbolAddress((void**)&W2h, g_W2thi);
    cudaGetSymbolAddress((void**)&W2l, g_W2tlo);
    cudaGetSymbolAddress((void**)&A1h, g_A1thi);
    cudaGetSymbolAddress((void**)&A1l, g_A1tlo);
    cudaGetSymbolAddress((void**)&h1h, g_h1hi);
    cudaGetSymbolAddress((void**)&h1l, g_h1lo);

    static int smem_set = 0;
    if (!smem_set) {
        cudaFuncSetAttribute((const void*)k_mma<256, 0, 0>,
                             cudaFuncAttributeMaxDynamicSharedMemorySize, GSMEM);
        cudaFuncSetAttribute((const void*)k_mma<256, 1, 1>,
                             cudaFuncAttributeMaxDynamicSharedMemorySize, GSMEM);
        cudaFuncSetAttribute((const void*)k_mma<128, 0, 1>,
                             cudaFuncAttributeMaxDynamicSharedMemorySize, GSMEM);
        smem_set = 1;
    }

    k_zero<<<4096, 512>>>();
    k_bn_stats<<<NT / 128, 256>>>(x_res);
    k_fold<<<H1DIM, IN_C>>>(W1, b1, bn_gamma, bn_beta);
    k_tw2<<<320, 256>>>(embed, W_msg);
    k_prep<<<192, 256>>>(W2, A1, a1);
    k_edges<<<(E + 255) / 256, 256>>>(edge_idx, E);

    // GEMM1: h1 = gelu(xn @ W1f + b1f) -> pre-split bf16 [NT x 256]
    k_mma<256, 0, 0><<<dim3(2, 256), 256, GSMEM>>>(
        x_res, nullptr, nullptr, W1h, W1l, b1fp, nullptr, h1h, h1l, H1DIM);
    // GEMM2: h2 = gelu(h1 @ W2 + b2) -> fp32 [NT x 128]
    k_mma<256, 1, 1><<<dim3(1, 256), 256, GSMEM>>>(
        nullptr, h1h, h1l, W2h, W2l, b2, h2p, nullptr, nullptr, DIM);
    // ids = argmax(h2 @ W3 + b3), flag near-ties
    k_logits_argmax<<<NT / 64, 256>>>(W3, b3);
    // fp32 recompute of flagged nodes
    k_fix<<<256, 256>>>(x_res, W2, b2, W3, b3);
    // z, coords
    k_agg<<<512, 256>>>(b_msg, w_coor, coords, out_z, out_coors);
    // GEMM3: t1 = gelu(z @ A1p + a1p) -> fp32 [NT x 128]
    k_mma<128, 0, 1><<<dim3(1, 256), 256, GSMEM>>>(
        out_z, nullptr, nullptr, A1h, A1l, a1pp, t1p, nullptr, nullptr, 128);
    // angles
    k_angles<<<NT / 64, 256>>>(A2, a2, dyt_alpha, dyt_w, dyt_b, out_angles);
}